// round 9
// baseline (speedup 1.0000x reference)
#include <cuda_runtime.h>
#include <cuda_fp16.h>
#include <cstdint>

#define BB 4
#define SS 2048
#define DD 128
#define CC 128
#define NCH 16
#define LDH 136       // half stride for 128-col tiles (272B rows)
#define LD2 72        // half stride for 64-col tiles (144B rows)

// ------------------- scratch (device globals; no allocs allowed) -------------------
__device__ __half g_phiK[BB*SS*DD];        // 2 MB
__device__ __half g_phiQ[BB*SS*DD];        // 2 MB
__device__ __half g_Vth [BB*SS*DD];        // 2 MB  V^T per chunk: [chunk][e][t]
__device__ __half g_ScTp[2][BB*NCH*DD*DD]; // 4 MB  partial chunk states (t-halves), half
__device__ float  g_ncp [2][BB*NCH*DD];
__device__ __half g_MpTh[BB*NCH*DD*DD];    // 2 MB  exclusive prefix, half
__device__ float  g_Np  [BB*NCH*DD];

// ------------------- helpers -------------------
__device__ __forceinline__ uint32_t sptr(const void* p){
    return (uint32_t)__cvta_generic_to_shared(p);
}

#define MMA16(d, a, b0v, b1v) \
    asm volatile("mma.sync.aligned.m16n8k16.row.col.f32.f16.f16.f32 " \
        "{%0,%1,%2,%3},{%4,%5,%6,%7},{%8,%9},{%0,%1,%2,%3};" \
        : "+f"(d[0]),"+f"(d[1]),"+f"(d[2]),"+f"(d[3]) \
        : "r"(a[0]),"r"(a[1]),"r"(a[2]),"r"(a[3]),"r"(b0v),"r"(b1v))

#define LDSMX4(r, addr) \
    asm volatile("ldmatrix.sync.aligned.m8n8.x4.shared.b16 {%0,%1,%2,%3},[%4];" \
        : "=r"((r)[0]),"=r"((r)[1]),"=r"((r)[2]),"=r"((r)[3]) : "r"(addr))

#define CP_ASYNC16(dst_u32, src_ptr) \
    asm volatile("cp.async.ca.shared.global [%0], [%1], 16;" :: "r"(dst_u32), "l"(src_ptr))
#define CP_COMMIT() asm volatile("cp.async.commit_group;")
#define CP_WAIT(n)  asm volatile("cp.async.wait_group %0;" :: "n"(n))

#define FRAG_OFFS() \
    const int rowA  = lane & 15;                            \
    const int kofA  = (lane >> 4) * 8;                      \
    const int rowB4 = (lane & 7) + ((lane >> 4) & 1) * 8;   \
    const int kofB4 = ((lane >> 3) & 1) * 8;                \
    const int er    = lane >> 2;                            \
    const int ec    = (lane & 3) * 2;

#define LOADA1_S(dst, u, r0, k0, LDX) \
    LDSMX4(dst, (u) + (uint32_t)((((r0) + rowA)*(LDX) + (k0) + kofA) << 1));

#define LOADA2_S(dst, u, r0, k0, LDX) { \
    LDSMX4(dst[0], (u) + (uint32_t)((((r0) + rowA)*(LDX) + (k0) + kofA) << 1)); \
    LDSMX4(dst[1], (u) + (uint32_t)((((r0) + 16 + rowA)*(LDX) + (k0) + kofA) << 1)); }

#define LOADB32_S(dst8, u, n0, k0, LDX) { \
    LDSMX4((dst8),     (u) + (uint32_t)((((n0) + rowB4)*(LDX) + (k0) + kofB4) << 1)); \
    LDSMX4((dst8) + 4, (u) + (uint32_t)((((n0) + 16 + rowB4)*(LDX) + (k0) + kofB4) << 1)); }

#define LOADB16_S(dst4, u, n0, k0, LDX) \
    LDSMX4((dst4), (u) + (uint32_t)((((n0) + rowB4)*(LDX) + (k0) + kofB4) << 1));

// pipelined GEMM, 32x32 warp tile (acc[2][4][4]), NK k-iters of 16
#define GEMM_PIPE_24(acc, uA_, rA0, uB_, nB0, LDX, NK) { \
    uint32_t a_[2][2][4]; uint32_t b_[2][8]; \
    LOADA2_S(a_[0], uA_, rA0, 0, LDX); LOADB32_S(b_[0], uB_, nB0, 0, LDX); \
    _Pragma("unroll") \
    for (int kk = 0; kk < (NK); ++kk) { \
        const int cur = kk & 1, nxt = cur ^ 1; \
        if (kk < (NK)-1) { LOADA2_S(a_[nxt], uA_, rA0, (kk+1)*16, LDX); LOADB32_S(b_[nxt], uB_, nB0, (kk+1)*16, LDX); } \
        _Pragma("unroll") \
        for (int mi = 0; mi < 2; ++mi) \
            _Pragma("unroll") \
            for (int ni = 0; ni < 4; ++ni) \
                MMA16(acc[mi][ni], a_[cur][mi], b_[cur][2*ni], b_[cur][2*ni+1]); \
    } }

// ============================================================================
// Kernel 1 (uniform): each block = one 64-row t-half of a chunk.
// grid = 128 (64 chunks x 2 halves), 512 threads
// ============================================================================
__global__ void __launch_bounds__(512, 1)
phi_state_kernel(const float* __restrict__ K, const float* __restrict__ Q,
                 const float* __restrict__ W, const float* __restrict__ V) {
    extern __shared__ char smraw[];
    __half* Xs  = (__half*)smraw;              // [128][LDH]  rows 0-63: K, 64-127: Q
    __half* Ws  = Xs + DD*LDH;                 // [128][LDH]  W
    __half* Kt2 = Ws + DD*LDH;                 // [128][LD2]  phiK^T
    __half* Vt2 = Kt2 + DD*LD2;                // [128][LD2]  V^T
    float*  scale = (float*)(Vt2 + DD*LD2);    // [128]

    const int tid  = threadIdx.x;
    const int lane = tid & 31;
    const int wid  = tid >> 5;
    const int chunk = blockIdx.x >> 1, half = blockIdx.x & 1;
    const size_t rbase = (size_t)chunk*CC + half*64;

    const float* Kg = K + rbase*DD;
    const float* Qg = Q + rbase*DD;
    const float* Vg = V + rbase*DD;

    if (tid < 128) scale[tid] = 0.f;
    __syncthreads();

    #pragma unroll
    for (int it = 0; it < 8; ++it) {
        int i = tid + it*512;
        int t = i >> 5, d4 = i & 31;
        const float* src = (t < 64) ? (Kg + (size_t)t*DD) : (Qg + (size_t)(t-64)*DD);
        float4 v = reinterpret_cast<const float4*>(src)[d4];
        float ls = v.x*v.x + v.y*v.y + v.z*v.z + v.w*v.w;
        ls += __shfl_xor_sync(~0u, ls, 16);
        ls += __shfl_xor_sync(~0u, ls, 8);
        ls += __shfl_xor_sync(~0u, ls, 4);
        ls += __shfl_xor_sync(~0u, ls, 2);
        ls += __shfl_xor_sync(~0u, ls, 1);
        if (lane == 0) atomicAdd(&scale[t], ls);
        *reinterpret_cast<__half2*>(Xs + t*LDH + d4*4)     = __floats2half2_rn(v.x, v.y);
        *reinterpret_cast<__half2*>(Xs + t*LDH + d4*4 + 2) = __floats2half2_rn(v.z, v.w);
        float4 w = reinterpret_cast<const float4*>(W)[t*32 + d4];
        *reinterpret_cast<__half2*>(Ws + t*LDH + d4*4)     = __floats2half2_rn(w.x, w.y);
        *reinterpret_cast<__half2*>(Ws + t*LDH + d4*4 + 2) = __floats2half2_rn(w.z, w.w);
    }
    __syncthreads();
    if (tid < 128)
        scale[tid] = __expf(-0.5f * sqrtf(scale[tid])) * 0.08838834764831845f;

    float4 vreg[8];
    if (wid >= 8) {
        int q = tid - 256;
        #pragma unroll
        for (int it = 0; it < 8; ++it) {
            int i = q + it*256;
            vreg[it] = reinterpret_cast<const float4*>(Vg)[(size_t)(i & 63)*32 + (i >> 6)];
        }
    }
    __syncthreads();

    const int wm0 = (wid >> 2) * 32;
    const int wn0 = (wid & 3) * 32;
    FRAG_OFFS();
    const uint32_t uX = sptr(Xs), uW = sptr(Ws);
    const uint32_t uK2 = sptr(Kt2), uV2 = sptr(Vt2);

    float acc[2][4][4];
    #pragma unroll
    for (int mi = 0; mi < 2; ++mi)
        #pragma unroll
        for (int ni = 0; ni < 4; ++ni)
            #pragma unroll
            for (int q = 0; q < 4; ++q) acc[mi][ni][q] = 0.f;

    GEMM_PIPE_24(acc, uX, wm0, uW, wn0, LDH, 8);

    __half2 oph[2][4][2];
    #pragma unroll
    for (int mi = 0; mi < 2; ++mi) {
        int r0 = wm0 + mi*16 + er;
        float s0 = scale[r0], s1 = scale[r0 + 8];
        #pragma unroll
        for (int ni = 0; ni < 4; ++ni) {
            oph[mi][ni][0] = __floats2half2_rn(s0*__expf(acc[mi][ni][0]), s0*__expf(acc[mi][ni][1]));
            oph[mi][ni][1] = __floats2half2_rn(s1*__expf(acc[mi][ni][2]), s1*__expf(acc[mi][ni][3]));
        }
    }

    {
        __half* dst = (wm0 < 64) ? g_phiK : g_phiQ;
        int mofs    = (wm0 < 64) ? 0 : 64;
        #pragma unroll
        for (int mi = 0; mi < 2; ++mi) {
            int m = wm0 + mi*16 + er;
            size_t g0 = (rbase + (m - mofs)) * DD;
            #pragma unroll
            for (int ni = 0; ni < 4; ++ni) {
                int col = wn0 + ni*8 + ec;
                *reinterpret_cast<__half2*>(dst + g0 + col)        = oph[mi][ni][0];
                *reinterpret_cast<__half2*>(dst + g0 + 8*DD + col) = oph[mi][ni][1];
            }
        }
    }

    if (wm0 < 64) {
        #pragma unroll
        for (int mi = 0; mi < 2; ++mi) {
            int t0 = wm0 + mi*16 + er;
            #pragma unroll
            for (int ni = 0; ni < 4; ++ni) {
                int col = wn0 + ni*8 + ec;
                Kt2[(col  )*LD2 + t0]     = oph[mi][ni][0].x;
                Kt2[(col+1)*LD2 + t0]     = oph[mi][ni][0].y;
                Kt2[(col  )*LD2 + t0 + 8] = oph[mi][ni][1].x;
                Kt2[(col+1)*LD2 + t0 + 8] = oph[mi][ni][1].y;
            }
        }
    } else {
        __half* Vthg = g_Vth + (size_t)chunk*CC*DD + half*64;
        int q = tid - 256;
        #pragma unroll
        for (int it = 0; it < 8; ++it) {
            int i = q + it*256;
            int t = i & 63, d4 = i >> 6;
            float4 v = vreg[it];
            __half h0 = __float2half_rn(v.x), h1 = __float2half_rn(v.y);
            __half h2 = __float2half_rn(v.z), h3 = __float2half_rn(v.w);
            Vt2[(d4*4+0)*LD2 + t] = h0;
            Vt2[(d4*4+1)*LD2 + t] = h1;
            Vt2[(d4*4+2)*LD2 + t] = h2;
            Vt2[(d4*4+3)*LD2 + t] = h3;
            Vthg[(size_t)(d4*4+0)*128 + t] = h0;
            Vthg[(size_t)(d4*4+1)*128 + t] = h1;
            Vthg[(size_t)(d4*4+2)*128 + t] = h2;
            Vthg[(size_t)(d4*4+3)*128 + t] = h3;
        }
    }
    __syncthreads();

    float acc2[2][4][4];
    #pragma unroll
    for (int mi = 0; mi < 2; ++mi)
        #pragma unroll
        for (int ni = 0; ni < 4; ++ni)
            #pragma unroll
            for (int q = 0; q < 4; ++q) acc2[mi][ni][q] = 0.f;

    GEMM_PIPE_24(acc2, uV2, wm0, uK2, wn0, LD2, 4);

    __half* Sg = g_ScTp[half] + (size_t)chunk*DD*DD;
    #pragma unroll
    for (int mi = 0; mi < 2; ++mi) {
        int r0 = wm0 + mi*16 + er;
        #pragma unroll
        for (int ni = 0; ni < 4; ++ni) {
            int col = wn0 + ni*8 + ec;
            *reinterpret_cast<__half2*>(Sg + (size_t)r0*DD + col)     = __floats2half2_rn(acc2[mi][ni][0], acc2[mi][ni][1]);
            *reinterpret_cast<__half2*>(Sg + (size_t)(r0+8)*DD + col) = __floats2half2_rn(acc2[mi][ni][2], acc2[mi][ni][3]);
        }
    }

    if (tid < 128) {
        float s = 0.f;
        #pragma unroll 8
        for (int t = 0; t < 64; ++t) s += __half2float(Kt2[tid*LD2 + t]);
        g_ncp[half][(size_t)chunk*DD + tid] = s;
    }
}

// ============================================================================
// Kernel 2: exclusive prefix over chunks (fp32 accum from half partials).
// grid = 128 (4 b x 32 slabs), 256 threads, half2 per thread
// ============================================================================
__global__ void prefix_kernel() {
    const int b = blockIdx.x >> 5, slab = blockIdx.x & 31;
    const size_t base = (size_t)b*NCH*DD*DD;
    const int e0 = slab*512 + threadIdx.x*2;
    float a0 = 0.f, a1 = 0.f;
    for (int c = 0; c < NCH; ++c) {
        size_t off = base + (size_t)c*DD*DD + e0;
        *reinterpret_cast<__half2*>(&g_MpTh[off]) = __floats2half2_rn(a0, a1);
        __half2 p0 = *reinterpret_cast<const __half2*>(&g_ScTp[0][off]);
        __half2 p1 = *reinterpret_cast<const __half2*>(&g_ScTp[1][off]);
        a0 += __half2float(p0.x) + __half2float(p1.x);
        a1 += __half2float(p0.y) + __half2float(p1.y);
    }
    if (slab == 0 && threadIdx.x < 128) {
        float an = 0.f;
        int i = threadIdx.x;
        for (int c = 0; c < NCH; ++c) {
            size_t off = (size_t)(b*NCH + c)*DD + i;
            g_Np[off] = an;
            an += g_ncp[0][off] + g_ncp[1][off];
        }
    }
}

// ============================================================================
// Kernel 3: per-chunk output, T-SPLIT (64 t-rows per block, full e cols).
// grid = 128 (64 chunks x 2 t-halves), 512 threads
// ============================================================================
template<int SR>   // s-range: 64 (th=0) or 128 (th=1)
__device__ __forceinline__ void phaseA_t(
    uint32_t uQ, uint32_t uK, __half* As, int wm0, int th,
    int rowA, int kofA, int rowB4, int kofB4, int er, int ec, int wid)
{
    constexpr int NT = SR / 32;                 // n8-frag pairs per warp: 2 or 4
    const int wn0 = (wid & 3) * (SR / 4);
    float acc[NT][4];
    #pragma unroll
    for (int ni = 0; ni < NT; ++ni)
        #pragma unroll
        for (int q = 0; q < 4; ++q) acc[ni][q] = 0.f;

    uint32_t a_[2][4]; uint32_t b_[2][2*NT];
    LOADA1_S(a_[0], uQ, wm0, 0, LDH);
    if (NT == 4) { LOADB32_S(b_[0], uK, wn0, 0, LDH); } else { LOADB16_S(b_[0], uK, wn0, 0, LDH); }
    #pragma unroll
    for (int kk = 0; kk < 8; ++kk) {
        const int cur = kk & 1, nxt = cur ^ 1;
        if (kk < 7) {
            LOADA1_S(a_[nxt], uQ, wm0, (kk+1)*16, LDH);
            if (NT == 4) { LOADB32_S(b_[nxt], uK, wn0, (kk+1)*16, LDH); }
            else         { LOADB16_S(b_[nxt], uK, wn0, (kk+1)*16, LDH); }
        }
        #pragma unroll
        for (int ni = 0; ni < NT; ++ni)
            MMA16(acc[ni], a_[cur], b_[cur][2*ni], b_[cur][2*ni+1]);
    }

    const int tg0 = th*64 + wm0 + er;     // global t for rows er / er+8
    #pragma unroll
    for (int ni = 0; ni < NT; ++ni) {
        int s0 = wn0 + ni*8 + ec;
        float v0 = (s0     <= tg0)     ? acc[ni][0] : 0.f;
        float v1 = (s0 + 1 <= tg0)     ? acc[ni][1] : 0.f;
        float v2 = (s0     <= tg0 + 8) ? acc[ni][2] : 0.f;
        float v3 = (s0 + 1 <= tg0 + 8) ? acc[ni][3] : 0.f;
        *reinterpret_cast<__half2*>(As + (wm0 + er)*LDH + s0)     = __floats2half2_rn(v0, v1);
        *reinterpret_cast<__half2*>(As + (wm0 + er + 8)*LDH + s0) = __floats2half2_rn(v2, v3);
    }
}

template<int NKC>  // C-phase k-iters: 4 (th=0) or 8 (th=1)
__device__ __forceinline__ void phaseBC_t(
    uint32_t uQ, uint32_t uM, uint32_t uA, uint32_t uV,
    const float* rs, float* out, size_t row_base, int wm0,
    int rowA, int kofA, int rowB4, int kofB4, int er, int ec, int wid)
{
    const int wn0 = (wid & 3) * 32;
    float acc[4][4];
    #pragma unroll
    for (int ni = 0; ni < 4; ++ni)
        #pragma unroll
        for (int q = 0; q < 4; ++q) acc[ni][q] = 0.f;

    uint32_t a_[2][4]; uint32_t b_[2][8];
    LOADA1_S(a_[0], uQ, wm0, 0, LDH);
    LOADB32_S(b_[0], uM, wn0, 0, LDH);
    #pragma unroll
    for (int kk = 0; kk < 8 + NKC; ++kk) {
        const int cur = kk & 1, nxt = cur ^ 1;
        const int k1 = kk + 1;
        if (k1 < 8) {
            LOADA1_S(a_[nxt], uQ, wm0, k1*16, LDH);
            LOADB32_S(b_[nxt], uM, wn0, k1*16, LDH);
        } else if (k1 < 8 + NKC) {
            LOADA1_S(a_[nxt], uA, wm0, (k1-8)*16, LDH);
            LOADB32_S(b_[nxt], uV, wn0, (k1-8)*16, LDH);
        }
        #pragma unroll
        for (int ni = 0; ni < 4; ++ni)
            MMA16(acc[ni], a_[cur], b_[cur][2*ni], b_[cur][2*ni+1]);
    }

    float r0 = rs[wm0 + er];
    float inv0 = 1.f / (r0 + (r0 > 0.f ? 1e-6f : (r0 < 0.f ? -1e-6f : 0.f)));
    float r1 = rs[wm0 + er + 8];
    float inv1 = 1.f / (r1 + (r1 > 0.f ? 1e-6f : (r1 < 0.f ? -1e-6f : 0.f)));
    size_t row0 = row_base + wm0 + er;
    #pragma unroll
    for (int ni = 0; ni < 4; ++ni) {
        int col = wn0 + ni*8 + ec;
        *reinterpret_cast<float2*>(out + row0*DD + col) =
            make_float2(acc[ni][0]*inv0, acc[ni][1]*inv0);
        *reinterpret_cast<float2*>(out + (row0 + 8)*DD + col) =
            make_float2(acc[ni][2]*inv1, acc[ni][3]*inv1);
    }
}

__global__ void __launch_bounds__(512, 1)
output_kernel(float* __restrict__ out) {
    extern __shared__ char smraw[];
    __half* Qs = (__half*)smraw;         // [64][LDH]  phiQ rows of this t-half
    __half* Ks = Qs + 64*LDH;            // [128][LDH] phiK rows s < SR
    __half* As = Ks + DD*LDH;            // [64][LDH]  masked A
    __half* Ms = As + 64*LDH;            // [128][LDH] Mp^T full
    __half* Vs = Ms + DD*LDH;            // [128][LDH] V^T (cols s < SR)
    float*  rs = (float*)(Vs + DD*LDH);  // [64]
    float*  Np = rs + 64;                // [128]

    const int tid = threadIdx.x, lane = tid & 31, wid = tid >> 5;
    const int chunk = blockIdx.x >> 1, th = blockIdx.x & 1;
    const int srange = 64 * (th + 1);

    const __half* Qg = g_phiQ + ((size_t)chunk*CC + th*64)*DD;
    const __half* Kg = g_phiK + (size_t)chunk*CC*DD;
    const __half* Mg = g_MpTh + (size_t)chunk*DD*DD;
    const __half* Vg = g_Vth  + (size_t)chunk*CC*DD;

    const uint32_t uQ = sptr(Qs), uK = sptr(Ks), uA = sptr(As);
    const uint32_t uM = sptr(Ms), uV = sptr(Vs);

    // group 0: Q (64 rows) + K (srange rows)
    #pragma unroll
    for (int it = 0; it < 2; ++it) {
        int i = tid + it*512;
        int t = i >> 4, c8 = i & 15;
        CP_ASYNC16(uQ + t*(LDH*2) + c8*16, Qg + t*128 + c8*8);
    }
    for (int i = tid; i < srange*16; i += 512) {
        int t = i >> 4, c8 = i & 15;
        CP_ASYNC16(uK + t*(LDH*2) + c8*16, Kg + t*128 + c8*8);
    }
    CP_COMMIT();
    // group 1: Mp (128 rows full) + V^T (128 rows x srange cols)
    #pragma unroll
    for (int it = 0; it < 4; ++it) {
        int i = tid + it*512;
        int e = i >> 4, c8 = i & 15;
        CP_ASYNC16(uM + e*(LDH*2) + c8*16, Mg + e*128 + c8*8);
    }
    {
        const int vsh = 3 + th, vmask = (srange >> 3) - 1;    // chunks of 8 halfs
        for (int i = tid; i < 128*(srange >> 3); i += 512) {
            int e = i >> vsh, c = i & vmask;
            CP_ASYNC16(uV + e*(LDH*2) + c*16, Vg + e*128 + c*8);
        }
    }
    CP_COMMIT();

    if (tid < 64) rs[tid] = 0.f;
    if (tid < 128) Np[tid] = g_Np[(size_t)chunk*DD + tid];
    CP_WAIT(1);
    __syncthreads();

    const int wm0 = (wid >> 2) * 16;
    FRAG_OFFS();

    if (th)
        phaseA_t<128>(uQ, uK, As, wm0, th, rowA, kofA, rowB4, kofB4, er, ec, wid);
    else
        phaseA_t<64>(uQ, uK, As, wm0, th, rowA, kofA, rowB4, kofB4, er, ec, wid);
    __syncthreads();

    // denominators: t local (64), 8 groups split s/d ranges
    {
        int t = tid & 63, p = tid >> 6;            // p = 0..7
        float r = 0.f;
        const int sw = srange >> 3;                // 8 or 16
        const int s0 = p * sw;
        for (int s = s0; s < s0 + sw; s += 2) {
            float2 f = __half22float2(*reinterpret_cast<__half2*>(As + t*LDH + s));
            r += f.x + f.y;
        }
        const int d0 = p * 16;
        #pragma unroll
        for (int d = d0; d < d0 + 16; ++d)
            r = fmaf(__half2float(Qs[t*LDH + d]), Np[d], r);
        atomicAdd(&rs[t], r);
    }
    CP_WAIT(0);
    __syncthreads();

    size_t row_base = (size_t)chunk*CC + th*64;
    if (th)
        phaseBC_t<8>(uQ, uM, uA, uV, rs, out, row_base, wm0, rowA, kofA, rowB4, kofB4, er, ec, wid);
    else
        phaseBC_t<4>(uQ, uM, uA, uV, rs, out, row_base, wm0, rowA, kofA, rowB4, kofB4, er, ec, wid);
}

// ============================================================================
extern "C" void kernel_launch(void* const* d_in, const int* in_sizes, int n_in,
                              void* d_out, int out_size) {
    const float* K = (const float*)d_in[0];
    const float* Q = (const float*)d_in[1];
    const float* V = (const float*)d_in[2];
    const float* W = (const float*)d_in[6];
    float* out = (float*)d_out;

    const int SMEM1 = 2*DD*LDH*2 + 2*DD*LD2*2 + 512;     // ~107 KB
    const int SMEM3 = (64+128+64+128+128)*LDH*2 + 1024;  // ~140 KB

    cudaFuncSetAttribute(phi_state_kernel, cudaFuncAttributeMaxDynamicSharedMemorySize, SMEM1);
    cudaFuncSetAttribute(output_kernel,    cudaFuncAttributeMaxDynamicSharedMemorySize, SMEM3);

    phi_state_kernel<<<128, 512, SMEM1>>>(K, Q, W, V);
    prefix_kernel<<<128, 256>>>();
    output_kernel<<<128, 512, SMEM3>>>(out);
}

// round 11
// speedup vs baseline: 1.4791x; 1.4791x over previous
#include <cuda_runtime.h>
#include <cuda_fp16.h>
#include <cstdint>

#define BB 4
#define SS 2048
#define DD 128
#define CC 128
#define NCH 16
#define LDH 136       // half stride for 128-col tiles (272B rows)
#define LD2 72        // half stride for 64-col tiles (144B rows)

// ------------------- scratch (device globals; no allocs allowed) -------------------
__device__ __half g_phiK[BB*SS*DD];        // 2 MB
__device__ __half g_phiQ[BB*SS*DD];        // 2 MB
__device__ __half g_Vth [BB*SS*DD];        // 2 MB  V^T per chunk: [chunk][e][t]
__device__ float  g_ScTp[2][BB*NCH*DD*DD]; // 8 MB  partial chunk states (t-halves)
__device__ float  g_ncp [2][BB*NCH*DD];
__device__ __half g_MpTh[BB*NCH*DD*DD];    // 2 MB  exclusive prefix, half
__device__ float  g_Np  [BB*NCH*DD];

// ------------------- helpers -------------------
__device__ __forceinline__ uint32_t sptr(const void* p){
    return (uint32_t)__cvta_generic_to_shared(p);
}
__device__ __forceinline__ uint32_t h2_bits(__half2 h){
    uint32_t u; __builtin_memcpy(&u, &h, 4); return u;
}

#define MMA16(d, a, b0v, b1v) \
    asm volatile("mma.sync.aligned.m16n8k16.row.col.f32.f16.f16.f32 " \
        "{%0,%1,%2,%3},{%4,%5,%6,%7},{%8,%9},{%0,%1,%2,%3};" \
        : "+f"(d[0]),"+f"(d[1]),"+f"(d[2]),"+f"(d[3]) \
        : "r"(a[0]),"r"(a[1]),"r"(a[2]),"r"(a[3]),"r"(b0v),"r"(b1v))

#define LDSMX4(r, addr) \
    asm volatile("ldmatrix.sync.aligned.m8n8.x4.shared.b16 {%0,%1,%2,%3},[%4];" \
        : "=r"((r)[0]),"=r"((r)[1]),"=r"((r)[2]),"=r"((r)[3]) : "r"(addr))

#define CP_ASYNC16(dst_u32, src_ptr) \
    asm volatile("cp.async.ca.shared.global [%0], [%1], 16;" :: "r"(dst_u32), "l"(src_ptr))
#define CP_COMMIT() asm volatile("cp.async.commit_group;")
#define CP_WAIT(n)  asm volatile("cp.async.wait_group %0;" :: "n"(n))

#define FRAG_OFFS() \
    const int rowA  = lane & 15;                            \
    const int kofA  = (lane >> 4) * 8;                      \
    const int rowB4 = (lane & 7) + ((lane >> 4) & 1) * 8;   \
    const int kofB4 = ((lane >> 3) & 1) * 8;                \
    const int er    = lane >> 2;                            \
    const int ec    = (lane & 3) * 2;

#define LOADA2_S(dst, u, r0, k0, LDX) { \
    LDSMX4(dst[0], (u) + (uint32_t)((((r0) + rowA)*(LDX) + (k0) + kofA) << 1)); \
    LDSMX4(dst[1], (u) + (uint32_t)((((r0) + 16 + rowA)*(LDX) + (k0) + kofA) << 1)); }

#define LOADB32_S(dst8, u, n0, k0, LDX) { \
    LDSMX4((dst8),     (u) + (uint32_t)((((n0) + rowB4)*(LDX) + (k0) + kofB4) << 1)); \
    LDSMX4((dst8) + 4, (u) + (uint32_t)((((n0) + 16 + rowB4)*(LDX) + (k0) + kofB4) << 1)); }

#define LOADB16_S(dst4, u, n0, k0, LDX) \
    LDSMX4((dst4), (u) + (uint32_t)((((n0) + rowB4)*(LDX) + (k0) + kofB4) << 1));

// pipelined GEMM, 32x32 warp tile (acc[2][4][4]), NK k-iters of 16
#define GEMM_PIPE_24(acc, uA_, rA0, uB_, nB0, LDX, NK) { \
    uint32_t a_[2][2][4]; uint32_t b_[2][8]; \
    LOADA2_S(a_[0], uA_, rA0, 0, LDX); LOADB32_S(b_[0], uB_, nB0, 0, LDX); \
    _Pragma("unroll") \
    for (int kk = 0; kk < (NK); ++kk) { \
        const int cur = kk & 1, nxt = cur ^ 1; \
        if (kk < (NK)-1) { LOADA2_S(a_[nxt], uA_, rA0, (kk+1)*16, LDX); LOADB32_S(b_[nxt], uB_, nB0, (kk+1)*16, LDX); } \
        _Pragma("unroll") \
        for (int mi = 0; mi < 2; ++mi) \
            _Pragma("unroll") \
            for (int ni = 0; ni < 4; ++ni) \
                MMA16(acc[mi][ni], a_[cur][mi], b_[cur][2*ni], b_[cur][2*ni+1]); \
    } }

// ============================================================================
// Kernel 1 (uniform): each block = one 64-row t-half of a chunk.
// phi over [64 K rows ; 64 Q rows] stacked (one 128x128x128 GEMM),
// then k=64 partial chunk state for this t-half.
// grid = 128 (64 chunks x 2 halves), 512 threads
// ============================================================================
__global__ void __launch_bounds__(512, 1)
phi_state_kernel(const float* __restrict__ K, const float* __restrict__ Q,
                 const float* __restrict__ W, const float* __restrict__ V) {
    extern __shared__ char smraw[];
    __half* Xs  = (__half*)smraw;              // [128][LDH]  rows 0-63: K, 64-127: Q
    __half* Ws  = Xs + DD*LDH;                 // [128][LDH]  W
    __half* Kt2 = Ws + DD*LDH;                 // [128][LD2]  phiK^T
    __half* Vt2 = Kt2 + DD*LD2;                // [128][LD2]  V^T
    float*  scale = (float*)(Vt2 + DD*LD2);    // [128]

    const int tid  = threadIdx.x;
    const int lane = tid & 31;
    const int wid  = tid >> 5;
    const int chunk = blockIdx.x >> 1, half = blockIdx.x & 1;
    const size_t rbase = (size_t)chunk*CC + half*64;

    const float* Kg = K + rbase*DD;
    const float* Qg = Q + rbase*DD;
    const float* Vg = V + rbase*DD;

    if (tid < 128) scale[tid] = 0.f;
    __syncthreads();

    #pragma unroll
    for (int it = 0; it < 8; ++it) {
        int i = tid + it*512;
        int t = i >> 5, d4 = i & 31;
        const float* src = (t < 64) ? (Kg + (size_t)t*DD) : (Qg + (size_t)(t-64)*DD);
        float4 v = reinterpret_cast<const float4*>(src)[d4];
        float ls = v.x*v.x + v.y*v.y + v.z*v.z + v.w*v.w;
        ls += __shfl_xor_sync(~0u, ls, 16);
        ls += __shfl_xor_sync(~0u, ls, 8);
        ls += __shfl_xor_sync(~0u, ls, 4);
        ls += __shfl_xor_sync(~0u, ls, 2);
        ls += __shfl_xor_sync(~0u, ls, 1);
        if (lane == 0) atomicAdd(&scale[t], ls);
        *reinterpret_cast<__half2*>(Xs + t*LDH + d4*4)     = __floats2half2_rn(v.x, v.y);
        *reinterpret_cast<__half2*>(Xs + t*LDH + d4*4 + 2) = __floats2half2_rn(v.z, v.w);
        float4 w = reinterpret_cast<const float4*>(W)[t*32 + d4];
        *reinterpret_cast<__half2*>(Ws + t*LDH + d4*4)     = __floats2half2_rn(w.x, w.y);
        *reinterpret_cast<__half2*>(Ws + t*LDH + d4*4 + 2) = __floats2half2_rn(w.z, w.w);
    }
    __syncthreads();
    if (tid < 128)
        scale[tid] = __expf(-0.5f * sqrtf(scale[tid])) * 0.08838834764831845f;

    // Q-warps prefetch V (64 rows of this t-half); latency hides under GEMM1
    float4 vreg[8];
    if (wid >= 8) {
        int q = tid - 256;
        #pragma unroll
        for (int it = 0; it < 8; ++it) {
            int i = q + it*256;
            vreg[it] = reinterpret_cast<const float4*>(Vg)[(size_t)(i & 63)*32 + (i >> 6)];
        }
    }
    __syncthreads();

    const int wm0 = (wid >> 2) * 32;       // warps 0-7: K rows (0-63); 8-15: Q rows (64-127)
    const int wn0 = (wid & 3) * 32;
    FRAG_OFFS();
    const uint32_t uX = sptr(Xs), uW = sptr(Ws);
    const uint32_t uK2 = sptr(Kt2), uV2 = sptr(Vt2);

    float acc[2][4][4];
    #pragma unroll
    for (int mi = 0; mi < 2; ++mi)
        #pragma unroll
        for (int ni = 0; ni < 4; ++ni)
            #pragma unroll
            for (int q = 0; q < 4; ++q) acc[mi][ni][q] = 0.f;

    GEMM_PIPE_24(acc, uX, wm0, uW, wn0, LDH, 8);

    __half2 oph[2][4][2];
    #pragma unroll
    for (int mi = 0; mi < 2; ++mi) {
        int r0 = wm0 + mi*16 + er;
        float s0 = scale[r0], s1 = scale[r0 + 8];
        #pragma unroll
        for (int ni = 0; ni < 4; ++ni) {
            oph[mi][ni][0] = __floats2half2_rn(s0*__expf(acc[mi][ni][0]), s0*__expf(acc[mi][ni][1]));
            oph[mi][ni][1] = __floats2half2_rn(s1*__expf(acc[mi][ni][2]), s1*__expf(acc[mi][ni][3]));
        }
    }

    // write phi to gmem (K warps -> g_phiK, Q warps -> g_phiQ)
    {
        __half* dst = (wm0 < 64) ? g_phiK : g_phiQ;
        int mofs    = (wm0 < 64) ? 0 : 64;
        #pragma unroll
        for (int mi = 0; mi < 2; ++mi) {
            int m = wm0 + mi*16 + er;
            size_t g0 = (rbase + (m - mofs)) * DD;
            #pragma unroll
            for (int ni = 0; ni < 4; ++ni) {
                int col = wn0 + ni*8 + ec;
                *reinterpret_cast<__half2*>(dst + g0 + col)        = oph[mi][ni][0];
                *reinterpret_cast<__half2*>(dst + g0 + 8*DD + col) = oph[mi][ni][1];
            }
        }
    }

    if (wm0 < 64) {
        // K warps: transpose phiK into Kt2 [d][t]
        #pragma unroll
        for (int mi = 0; mi < 2; ++mi) {
            int t0 = wm0 + mi*16 + er;
            #pragma unroll
            for (int ni = 0; ni < 4; ++ni) {
                int col = wn0 + ni*8 + ec;
                Kt2[(col  )*LD2 + t0]     = oph[mi][ni][0].x;
                Kt2[(col+1)*LD2 + t0]     = oph[mi][ni][0].y;
                Kt2[(col  )*LD2 + t0 + 8] = oph[mi][ni][1].x;
                Kt2[(col+1)*LD2 + t0 + 8] = oph[mi][ni][1].y;
            }
        }
    } else {
        // Q warps: V^T -> Vt2 (+ gmem half copy)
        __half* Vthg = g_Vth + (size_t)chunk*CC*DD + half*64;
        int q = tid - 256;
        #pragma unroll
        for (int it = 0; it < 8; ++it) {
            int i = q + it*256;
            int t = i & 63, d4 = i >> 6;
            float4 v = vreg[it];
            __half h0 = __float2half_rn(v.x), h1 = __float2half_rn(v.y);
            __half h2 = __float2half_rn(v.z), h3 = __float2half_rn(v.w);
            Vt2[(d4*4+0)*LD2 + t] = h0;
            Vt2[(d4*4+1)*LD2 + t] = h1;
            Vt2[(d4*4+2)*LD2 + t] = h2;
            Vt2[(d4*4+3)*LD2 + t] = h3;
            Vthg[(size_t)(d4*4+0)*128 + t] = h0;
            Vthg[(size_t)(d4*4+1)*128 + t] = h1;
            Vthg[(size_t)(d4*4+2)*128 + t] = h2;
            Vthg[(size_t)(d4*4+3)*128 + t] = h3;
        }
    }
    __syncthreads();

    // GEMM2 (partial, k=64): ScTp[e][d] = sum_{t in half} Vt2[e][t] * Kt2[d][t]
    float acc2[2][4][4];
    #pragma unroll
    for (int mi = 0; mi < 2; ++mi)
        #pragma unroll
        for (int ni = 0; ni < 4; ++ni)
            #pragma unroll
            for (int q = 0; q < 4; ++q) acc2[mi][ni][q] = 0.f;

    GEMM_PIPE_24(acc2, uV2, wm0, uK2, wn0, LD2, 4);

    float* Sg = g_ScTp[half] + (size_t)chunk*DD*DD;
    #pragma unroll
    for (int mi = 0; mi < 2; ++mi) {
        int r0 = wm0 + mi*16 + er;
        #pragma unroll
        for (int ni = 0; ni < 4; ++ni) {
            int col = wn0 + ni*8 + ec;
            *reinterpret_cast<float2*>(Sg + (size_t)r0*DD + col)     = make_float2(acc2[mi][ni][0], acc2[mi][ni][1]);
            *reinterpret_cast<float2*>(Sg + (size_t)(r0+8)*DD + col) = make_float2(acc2[mi][ni][2], acc2[mi][ni][3]);
        }
    }

    if (tid < 128) {
        float s = 0.f;
        #pragma unroll 8
        for (int t = 0; t < 64; ++t) s += __half2float(Kt2[tid*LD2 + t]);
        g_ncp[half][(size_t)chunk*DD + tid] = s;
    }
}

// ============================================================================
// Kernel 2: exclusive prefix over chunks (sums the two t-half partials).
// grid = 64 (4 b x 16 slabs), 256 threads, float4 per thread (full sectors)
// ============================================================================
__global__ void prefix_kernel() {
    const int b = blockIdx.x >> 4, slab = blockIdx.x & 15;
    const size_t base = (size_t)b*NCH*DD*DD;
    const int e0 = slab*1024 + threadIdx.x*4;
    float a0 = 0.f, a1 = 0.f, a2 = 0.f, a3 = 0.f;
    for (int c = 0; c < NCH; ++c) {
        size_t off = base + (size_t)c*DD*DD + e0;
        uint2 packed;
        packed.x = h2_bits(__floats2half2_rn(a0, a1));
        packed.y = h2_bits(__floats2half2_rn(a2, a3));
        *reinterpret_cast<uint2*>(&g_MpTh[off]) = packed;
        float4 p0 = *reinterpret_cast<const float4*>(&g_ScTp[0][off]);
        float4 p1 = *reinterpret_cast<const float4*>(&g_ScTp[1][off]);
        a0 += p0.x + p1.x;
        a1 += p0.y + p1.y;
        a2 += p0.z + p1.z;
        a3 += p0.w + p1.w;
    }
    if (slab == 0 && threadIdx.x < 128) {
        float an = 0.f;
        int i = threadIdx.x;
        for (int c = 0; c < NCH; ++c) {
            size_t off = (size_t)(b*NCH + c)*DD + i;
            g_Np[off] = an;
            an += g_ncp[0][off] + g_ncp[1][off];
        }
    }
}

// ============================================================================
// Kernel 3: per-chunk output, split on output columns (j-split).
// grid = 128 (64 chunks x 2 j-halves), 512 threads, cp.async prefetch
// ============================================================================
__global__ void __launch_bounds__(512, 1)
output_kernel(float* __restrict__ out) {
    extern __shared__ char smraw[];
    __half* Qs = (__half*)smraw;         // [128][LDH] phiQ
    __half* Bs = Qs + DD*LDH;            // [128][LDH] phiK
    __half* As = Bs + DD*LDH;            // [128][LDH] masked A [t][s]
    __half* Ms = As + DD*LDH;            // [64][LDH]  Mp half-tile
    __half* Vs = Ms + 64*LDH;            // [64][LDH]  V^T half-tile
    float*  rs = (float*)(Vs + 64*LDH);  // [128]
    float*  Np = rs + 128;               // [128]

    const int tid = threadIdx.x, lane = tid & 31, wid = tid >> 5;
    const int chunk = blockIdx.x >> 1, h = blockIdx.x & 1;
    const int b = chunk / NCH, ch = chunk % NCH;
    const int j0h = h * 64;

    const __half* Qg = g_phiQ + (size_t)chunk*CC*DD;
    const __half* Kg = g_phiK + (size_t)chunk*CC*DD;
    const __half* Mg = g_MpTh + (size_t)chunk*DD*DD + (size_t)j0h*DD;
    const __half* Vg = g_Vth  + (size_t)chunk*CC*DD + (size_t)j0h*DD;

    const uint32_t uQ = sptr(Qs), uB = sptr(Bs), uA = sptr(As);
    const uint32_t uM = sptr(Ms), uV = sptr(Vs);

    #pragma unroll
    for (int it = 0; it < 4; ++it) {
        int i = tid + it*512;
        int t = i >> 4, c8 = i & 15;
        CP_ASYNC16(uQ + t*(LDH*2) + c8*16, Qg + t*128 + c8*8);
        CP_ASYNC16(uB + t*(LDH*2) + c8*16, Kg + t*128 + c8*8);
    }
    CP_COMMIT();
    #pragma unroll
    for (int it = 0; it < 2; ++it) {
        int i = tid + it*512;
        int e = i >> 4, c8 = i & 15;
        CP_ASYNC16(uM + e*(LDH*2) + c8*16, Mg + e*128 + c8*8);
        CP_ASYNC16(uV + e*(LDH*2) + c8*16, Vg + e*128 + c8*8);
    }
    CP_COMMIT();

    if (tid < 128) {
        rs[tid] = 0.f;
        Np[tid] = g_Np[(size_t)chunk*DD + tid];
    }
    CP_WAIT(1);
    __syncthreads();

    const int wm0 = (wid >> 2) * 32;
    FRAG_OFFS();

    // ---- Phase A ----
    {
        const int wn0 = (wid & 3) * 32;
        float acc[2][4][4];
        #pragma unroll
        for (int mi = 0; mi < 2; ++mi)
            #pragma unroll
            for (int ni = 0; ni < 4; ++ni)
                #pragma unroll
                for (int q = 0; q < 4; ++q) acc[mi][ni][q] = 0.f;

        GEMM_PIPE_24(acc, uQ, wm0, uB, wn0, LDH, 8);

        #pragma unroll
        for (int mi = 0; mi < 2; ++mi) {
            int t0 = wm0 + mi*16 + er;
            int t1 = t0 + 8;
            #pragma unroll
            for (int ni = 0; ni < 4; ++ni) {
                int s0 = wn0 + ni*8 + ec;
                float v0 = (s0     <= t0) ? acc[mi][ni][0] : 0.f;
                float v1 = (s0 + 1 <= t0) ? acc[mi][ni][1] : 0.f;
                float v2 = (s0     <= t1) ? acc[mi][ni][2] : 0.f;
                float v3 = (s0 + 1 <= t1) ? acc[mi][ni][3] : 0.f;
                *reinterpret_cast<__half2*>(As + t0*LDH + s0) = __floats2half2_rn(v0, v1);
                *reinterpret_cast<__half2*>(As + t1*LDH + s0) = __floats2half2_rn(v2, v3);
            }
        }
    }
    __syncthreads();

    // ---- denominators ----
    {
        int t = tid & 127, p = tid >> 7;
        float r = 0.f;
        const int s0 = p * 32;
        #pragma unroll 8
        for (int s = s0; s < s0 + 32; s += 2) {
            float2 f = __half22float2(*reinterpret_cast<__half2*>(As + t*LDH + s));
            r += f.x + f.y;
        }
        #pragma unroll 8
        for (int d = s0; d < s0 + 32; ++d)
            r = fmaf(__half2float(Qs[t*LDH + d]), Np[d], r);
        atomicAdd(&rs[t], r);
    }
    CP_WAIT(0);
    __syncthreads();

    // ---- Phase B+C ----
    {
        const int wn0 = (wid & 3) * 16;
        float acc[2][2][4];
        #pragma unroll
        for (int mi = 0; mi < 2; ++mi)
            #pragma unroll
            for (int ni = 0; ni < 2; ++ni)
                #pragma unroll
                for (int q = 0; q < 4; ++q) acc[mi][ni][q] = 0.f;

        uint32_t a_[2][2][4]; uint32_t b_[2][4];
        LOADA2_S(a_[0], uQ, wm0, 0, LDH);
        LOADB16_S(b_[0], uM, wn0, 0, LDH);
        #pragma unroll
        for (int kk = 0; kk < 16; ++kk) {
            const int cur = kk & 1, nxt = cur ^ 1;
            const int k1 = kk + 1;
            if (k1 < 8) {
                LOADA2_S(a_[nxt], uQ, wm0, k1*16, LDH);
                LOADB16_S(b_[nxt], uM, wn0, k1*16, LDH);
            } else if (k1 < 16) {
                LOADA2_S(a_[nxt], uA, wm0, (k1-8)*16, LDH);
                LOADB16_S(b_[nxt], uV, wn0, (k1-8)*16, LDH);
            }
            #pragma unroll
            for (int mi = 0; mi < 2; ++mi)
                #pragma unroll
                for (int ni = 0; ni < 2; ++ni)
                    MMA16(acc[mi][ni], a_[cur][mi], b_[cur][2*ni], b_[cur][2*ni+1]);
        }

        #pragma unroll
        for (int mi = 0; mi < 2; ++mi) {
            int t0 = wm0 + mi*16 + er;
            float r0 = rs[t0];
            float inv0 = 1.f / (r0 + (r0 > 0.f ? 1e-6f : (r0 < 0.f ? -1e-6f : 0.f)));
            float r1 = rs[t0 + 8];
            float inv1 = 1.f / (r1 + (r1 > 0.f ? 1e-6f : (r1 < 0.f ? -1e-6f : 0.f)));
            size_t row0 = (size_t)b*SS + (size_t)ch*CC + t0;
            #pragma unroll
            for (int ni = 0; ni < 2; ++ni) {
                int col = j0h + wn0 + ni*8 + ec;
                *reinterpret_cast<float2*>(out + row0*DD + col) =
                    make_float2(acc[mi][ni][0]*inv0, acc[mi][ni][1]*inv0);
                *reinterpret_cast<float2*>(out + (row0 + 8)*DD + col) =
                    make_float2(acc[mi][ni][2]*inv1, acc[mi][ni][3]*inv1);
            }
        }
    }
}

// ============================================================================
extern "C" void kernel_launch(void* const* d_in, const int* in_sizes, int n_in,
                              void* d_out, int out_size) {
    const float* K = (const float*)d_in[0];
    const float* Q = (const float*)d_in[1];
    const float* V = (const float*)d_in[2];
    const float* W = (const float*)d_in[6];
    float* out = (float*)d_out;

    const int SMEM1 = 2*DD*LDH*2 + 2*DD*LD2*2 + 512;     // ~107 KB
    const int SMEM3 = 3*DD*LDH*2 + 2*64*LDH*2 + 1024;    // ~141 KB

    cudaFuncSetAttribute(phi_state_kernel, cudaFuncAttributeMaxDynamicSharedMemorySize, SMEM1);
    cudaFuncSetAttribute(output_kernel,    cudaFuncAttributeMaxDynamicSharedMemorySize, SMEM3);

    phi_state_kernel<<<128, 512, SMEM1>>>(K, Q, W, V);
    prefix_kernel<<<64, 256>>>();
    output_kernel<<<128, 512, SMEM3>>>(out);
}